// round 14
// baseline (speedup 1.0000x reference)
#include <cuda_runtime.h>
#include <cuda_bf16.h>
#include <cuda_fp16.h>
#include <cstdint>

#define NTOK 4096
#define CDIM 1024
#define C3   3072
#define NH   16
#define HD   64
#define LWIN 512
#define NWIN 8

#define BN 128
#define BK 32
#define KDIM 1024
#define TSTEPS (KDIM / BK)         // 32
#define QKV_SMEM (3 * (64 * 80 + 10240))    // 46080
#define OUT_SMEM (3 * (128 * 80 + 10240))   // 61440

#define AKV 18432                  // attn K+V stage bytes (64*144*2)
#define ATTN_SMEM (9216 + 3 * AKV) // Q(64 rows) + 3-stage KV ring = 64512

// ---------------- scratch ----------------
__device__ __half g_qh[NTOK * CDIM];     // [w][h][l][d] fp16
__device__ __half g_kh[NTOK * CDIM];
__device__ __half g_vh[NTOK * CDIM];
__device__ __half g_as[NTOK * KDIM];     // GEMM A buffer (x, then attention O)
__device__ __half g_bs[4096 * KDIM];     // GEMM B: rows 0..3071 wqkv^T, 3072..4095 wout^T

// ---------------- helpers ----------------
__device__ __forceinline__ uint32_t su32(const void* p) {
    uint32_t a;
    asm("{ .reg .u64 t; cvta.to.shared.u64 t, %1; cvt.u32.u64 %0, t; }" : "=r"(a) : "l"(p));
    return a;
}
__device__ __forceinline__ void cp16(uint32_t dst, const void* src) {
    asm volatile("cp.async.cg.shared.global [%0], [%1], 16;" :: "r"(dst), "l"(src));
}
__device__ __forceinline__ void ldm_x4(uint32_t* r, uint32_t addr) {
    asm volatile("ldmatrix.sync.aligned.m8n8.x4.shared.b16 {%0,%1,%2,%3}, [%4];"
                 : "=r"(r[0]), "=r"(r[1]), "=r"(r[2]), "=r"(r[3]) : "r"(addr));
}
__device__ __forceinline__ void ldm_x4t(uint32_t* r, uint32_t addr) {
    asm volatile("ldmatrix.sync.aligned.m8n8.x4.trans.shared.b16 {%0,%1,%2,%3}, [%4];"
                 : "=r"(r[0]), "=r"(r[1]), "=r"(r[2]), "=r"(r[3]) : "r"(addr));
}
__device__ __forceinline__ void ldm_x2(uint32_t* r, uint32_t addr) {
    asm volatile("ldmatrix.sync.aligned.m8n8.x2.shared.b16 {%0,%1}, [%2];"
                 : "=r"(r[0]), "=r"(r[1]) : "r"(addr));
}
__device__ __forceinline__ void mma_f16(float* c, const uint32_t* a, const uint32_t* b) {
    asm volatile("mma.sync.aligned.m16n8k16.row.col.f32.f16.f16.f32 "
                 "{%0,%1,%2,%3}, {%4,%5,%6,%7}, {%8,%9}, {%0,%1,%2,%3};"
                 : "+f"(c[0]), "+f"(c[1]), "+f"(c[2]), "+f"(c[3])
                 : "r"(a[0]), "r"(a[1]), "r"(a[2]), "r"(a[3]), "r"(b[0]), "r"(b[1]));
}

// ---------------- merged conversion kernel ----------------
// blocks 0..4095: x -> g_as (fp16). blocks 4096..8191: weight transpose.
__global__ __launch_bounds__(256) void k_conv_all(const float* __restrict__ x,
                                                  const float* __restrict__ wqkv,
                                                  const float* __restrict__ wout) {
    int bx = blockIdx.x;
    int tid = threadIdx.x;
    if (bx < 4096) {
        int idx = (bx * 256 + tid) << 2;
        float4 v = *(const float4*)&x[idx];
        __half2 h0 = __floats2half2_rn(v.x, v.y);
        __half2 h1 = __floats2half2_rn(v.z, v.w);
        uint2 hv;
        hv.x = *(uint32_t*)&h0;
        hv.y = *(uint32_t*)&h1;
        *(uint2*)(g_as + idx) = hv;
    } else {
        __shared__ float s[32][33];
        int b = bx - 4096;
        int tx = tid & 31, ty = tid >> 5;
        int bxx = b & 127, byy = b >> 7;
        const float* w;
        int N, n0;
        size_t off;
        if (bxx < 96) { w = wqkv; N = C3;   n0 = bxx * 32;        off = 0; }
        else          { w = wout; N = CDIM; n0 = (bxx - 96) * 32; off = (size_t)3072 * KDIM; }
        int k0 = byy * 32;
#pragma unroll
        for (int r = 0; r < 4; r++)
            s[ty + 8 * r][tx] = w[(size_t)(k0 + ty + 8 * r) * N + n0 + tx];
        __syncthreads();
#pragma unroll
        for (int r = 0; r < 4; r++) {
            int n = n0 + ty + 8 * r, k = k0 + tx;
            g_bs[off + (size_t)n * KDIM + k] = __float2half_rn(s[tx][ty + 8 * r]);
        }
    }
}

// ---------------- GEMM tile loader (AR = A rows per tile) ----------------
template <int AR>
__device__ __forceinline__ void issue_tile_t(const __half* __restrict__ A,
                                             const __half* __restrict__ B,
                                             int bm, int bn, int t,
                                             uint32_t sbase, int tid) {
    const int kt = t * BK;
#pragma unroll
    for (int p = 0; p < AR / 64; p++) {            // A: AR rows x 4 cp16
        int id = tid + p * 256;
        int row = id >> 2, cc = id & 3;
        cp16(sbase + row * 80 + cc * 16,
             A + (size_t)(bm + row) * KDIM + kt + cc * 8);
    }
#pragma unroll
    for (int p = 0; p < 2; p++) {                  // B: 128 rows x 4 cp16
        int id = tid + p * 256;
        int row = id >> 2, cc = id & 3;
        cp16(sbase + AR * 80 + row * 80 + cc * 16,
             B + (size_t)(bn + row) * KDIM + kt + cc * 8);
    }
    asm volatile("cp.async.commit_group;" ::: "memory");
}

// mainloop: MT = m16 tiles per warp (tile rows = MT*32, warps: wm in {0,1})
#define GEMM_MAINLOOP(Aptr, Bptr, MT)                                             \
    float c[MT][4][4];                                                            \
    _Pragma("unroll")                                                             \
    for (int mt = 0; mt < MT; mt++)                                               \
        _Pragma("unroll")                                                         \
        for (int nt = 0; nt < 4; nt++)                                            \
            _Pragma("unroll")                                                     \
            for (int q = 0; q < 4; q++) c[mt][nt][q] = 0.0f;                      \
    const int STG_ = (MT) * 32 * 80 + 10240;                                      \
    const uint32_t aoff = (uint32_t)((wm * ((MT) * 16) + (lane & 15)) * 80 + (lane >> 4) * 16); \
    const uint32_t boff = (uint32_t)((MT) * 32 * 80 + (wn * 32 + (lane & 7)) * 80 + ((lane >> 3) & 1) * 16); \
    issue_tile_t<(MT) * 32>(Aptr, Bptr, bm, bn, 0, base, tid);                    \
    issue_tile_t<(MT) * 32>(Aptr, Bptr, bm, bn, 1, base + STG_, tid);             \
    _Pragma("unroll 1")                                                           \
    for (int t = 0; t < TSTEPS; t++) {                                            \
        if (t + 1 < TSTEPS) asm volatile("cp.async.wait_group 1;" ::: "memory");  \
        else                asm volatile("cp.async.wait_group 0;" ::: "memory");  \
        __syncthreads();                                                          \
        if (t + 2 < TSTEPS)                                                       \
            issue_tile_t<(MT) * 32>(Aptr, Bptr, bm, bn, t + 2, base + ((t + 2) % 3) * STG_, tid); \
        const uint32_t stage = base + (t % 3) * STG_;                             \
        const uint32_t ab = stage + aoff;                                         \
        const uint32_t bb = stage + boff;                                         \
        _Pragma("unroll")                                                         \
        for (int ks = 0; ks < 2; ks++) {                                          \
            uint32_t af[MT][4], bf[4][2];                                         \
            _Pragma("unroll")                                                     \
            for (int mt = 0; mt < MT; mt++)                                       \
                ldm_x4(af[mt], ab + mt * (16 * 80) + ks * 32);                    \
            _Pragma("unroll")                                                     \
            for (int nt = 0; nt < 4; nt++)                                        \
                ldm_x2(bf[nt], bb + nt * (8 * 80) + ks * 32);                     \
            _Pragma("unroll")                                                     \
            for (int mt = 0; mt < MT; mt++)                                       \
                _Pragma("unroll")                                                 \
                for (int nt = 0; nt < 4; nt++)                                    \
                    mma_f16(c[mt][nt], af[mt], bf[nt]);                           \
        }                                                                         \
    }

// ---------------- qkv GEMM (BM=64) with fused RMS-norm + RoPE + permute -------
__global__ __launch_bounds__(256, 2)
void k_gemm_qkv(const float* __restrict__ bias, const int* __restrict__ coords,
                const float* __restrict__ qg, const float* __restrict__ kg) {
    extern __shared__ __align__(16) char gsm[];
    const uint32_t base = su32(gsm);
    const int tid = threadIdx.x, wid = tid >> 5, lane = tid & 31;
    const int wm = wid & 1, wn = wid >> 1;
    const int bm = blockIdx.y * 64, bn = blockIdx.x * BN;

    GEMM_MAINLOOP(g_as, g_bs, 2)

    // ---- fused epilogue ----
    __syncthreads();
    float* ssm = (float*)gsm;              // reuse: [wm(2)][wn(4)][32 rows]

    const int part  = bn >> 10;            // 0=q 1=k 2=v
    const int hglob = ((bn & 1023) >> 6) + (wn >> 1);
    const int c2    = (lane & 3) * 2;
    const int cihb  = (wn & 1) * 32 + c2;
    const int bcb   = bn + wn * 32 + c2;

    if (part < 2) {
        float ssv[2][2];
#pragma unroll
        for (int mt = 0; mt < 2; mt++) {
#pragma unroll
            for (int hf = 0; hf < 2; hf++) {
                float s = 0.0f;
#pragma unroll
                for (int nt = 0; nt < 4; nt++) {
                    float v0 = c[mt][nt][2 * hf]     + bias[bcb + nt * 8];
                    float v1 = c[mt][nt][2 * hf + 1] + bias[bcb + nt * 8 + 1];
                    s += v0 * v0 + v1 * v1;
                }
                s += __shfl_xor_sync(0xffffffffu, s, 1);
                s += __shfl_xor_sync(0xffffffffu, s, 2);
                ssv[mt][hf] = s;
            }
        }
        if ((lane & 3) == 0) {
#pragma unroll
            for (int mt = 0; mt < 2; mt++)
#pragma unroll
                for (int hf = 0; hf < 2; hf++)
                    ssm[(wm * 4 + wn) * 32 + mt * 16 + hf * 8 + (lane >> 2)] = ssv[mt][hf];
        }
        __syncthreads();

        const float* gam = (part == 0) ? qg : kg;
        __half* dst = (part == 0) ? g_qh : g_kh;
#pragma unroll
        for (int mt = 0; mt < 2; mt++) {
#pragma unroll
            for (int hf = 0; hf < 2; hf++) {
                int ridx = mt * 16 + hf * 8 + (lane >> 2);
                float tot = ssv[mt][hf] + ssm[(wm * 4 + (wn ^ 1)) * 32 + ridx];
                float inv = 8.0f / fmaxf(sqrtf(tot), 1e-12f);
                int n = bm + wm * 32 + ridx;
                int4 cd = *(const int4*)&coords[n * 4];
                int z = cd.y, y = cd.z, x = cd.w;
                int w = ((z >> 3) * 2 + (y >> 3)) * 2 + (x >> 3);
                int l = ((z & 7) * 8 + (y & 7)) * 8 + (x & 7);
                size_t ob = ((size_t)(w * NH + hglob) * LWIN + l) * HD;
#pragma unroll
                for (int nt = 0; nt < 4; nt++) {
                    int cih = cihb + nt * 8;
                    float re = (c[mt][nt][2 * hf]     + bias[bcb + nt * 8])     * inv * gam[hglob * HD + cih];
                    float im = (c[mt][nt][2 * hf + 1] + bias[bcb + nt * 8 + 1]) * inv * gam[hglob * HD + cih + 1];
                    int p = cih >> 1;
                    float cp = 1.0f, sp = 0.0f;
                    if (p < 30) {
                        int ax = p / 10, fi = p - ax * 10;
                        int cv = (ax == 0) ? z : (ax == 1) ? y : x;
                        __sincosf((float)cv * __expf(-(float)fi * 0.92103403719761836f), &sp, &cp);
                    }
                    *(__half2*)&dst[ob + cih] = __floats2half2_rn(re * cp - im * sp, re * sp + im * cp);
                }
            }
        }
    } else {
#pragma unroll
        for (int mt = 0; mt < 2; mt++) {
#pragma unroll
            for (int hf = 0; hf < 2; hf++) {
                int ridx = mt * 16 + hf * 8 + (lane >> 2);
                int n = bm + wm * 32 + ridx;
                int4 cd = *(const int4*)&coords[n * 4];
                int z = cd.y, y = cd.z, x = cd.w;
                int w = ((z >> 3) * 2 + (y >> 3)) * 2 + (x >> 3);
                int l = ((z & 7) * 8 + (y & 7)) * 8 + (x & 7);
                size_t ob = ((size_t)(w * NH + hglob) * LWIN + l) * HD;
#pragma unroll
                for (int nt = 0; nt < 4; nt++) {
                    int cih = cihb + nt * 8;
                    float v0 = c[mt][nt][2 * hf]     + bias[bcb + nt * 8];
                    float v1 = c[mt][nt][2 * hf + 1] + bias[bcb + nt * 8 + 1];
                    *(__half2*)&g_vh[ob + cih] = __floats2half2_rn(v0, v1);
                }
            }
        }
    }
}

// ---------------- out GEMM (BM=128, fp32 output) ----------------
__global__ __launch_bounds__(256, 2)
void k_gemm_out(const float* __restrict__ bias, float* __restrict__ C) {
    extern __shared__ __align__(16) char gsm[];
    const uint32_t base = su32(gsm);
    const int tid = threadIdx.x, wid = tid >> 5, lane = tid & 31;
    const int wm = wid & 1, wn = wid >> 1;
    const int bm = blockIdx.y * 128, bn = blockIdx.x * BN;
    const __half* Bw = g_bs + (size_t)3072 * KDIM;

    GEMM_MAINLOOP(g_as, Bw, 4)

    const int r0 = bm + wm * 64 + (lane >> 2);
    const int c0 = bn + wn * 32 + (lane & 3) * 2;
#pragma unroll
    for (int mt = 0; mt < 4; mt++) {
#pragma unroll
        for (int nt = 0; nt < 4; nt++) {
            int col = c0 + nt * 8;
            float bx = bias[col], by = bias[col + 1];
            int ra = r0 + mt * 16;
            *(float2*)&C[(size_t)ra * CDIM + col] =
                make_float2(c[mt][nt][0] + bx, c[mt][nt][1] + by);
            *(float2*)&C[(size_t)(ra + 8) * CDIM + col] =
                make_float2(c[mt][nt][2] + bx, c[mt][nt][3] + by);
        }
    }
}

// ---------------- fp16 flash attention (64-row tiles, 128 threads) ----------------
__device__ __forceinline__ void attn_ldkv(const __half* kb, const __half* vb, int t,
                                          uint32_t stage, int tid) {
#pragma unroll
    for (int p = 0; p < 4; p++) {
        int id = tid + p * 128;
        int row = id >> 3, c = id & 7;
        cp16(stage + row * 144 + c * 16,        kb + (size_t)(t * 64 + row) * HD + c * 8);
        cp16(stage + 9216 + row * 144 + c * 16, vb + (size_t)(t * 64 + row) * HD + c * 8);
    }
    asm volatile("cp.async.commit_group;" ::: "memory");
}

__global__ __launch_bounds__(128, 3)
void attn_mma() {
    extern __shared__ __half asmem[];
    const int tid = threadIdx.x, wid = tid >> 5, lane = tid & 31;
    const int wh = blockIdx.x, qt = blockIdx.y;

    const uint32_t sq  = su32(asmem);
    const uint32_t skv = sq + 64 * 144;     // 3-stage KV ring base

    const __half* qb = g_qh + ((size_t)wh * LWIN + qt * 64) * HD;
    const __half* kb = g_kh + (size_t)wh * LWIN * HD;
    const __half* vb = g_vh + (size_t)wh * LWIN * HD;

#pragma unroll
    for (int p = 0; p < 4; p++) {
        int id = tid + p * 128;
        int row = id >> 3, c = id & 7;
        cp16(sq + row * 144 + c * 16, qb + (size_t)row * HD + c * 8);
    }
    attn_ldkv(kb, vb, 0, skv, tid);
    attn_ldkv(kb, vb, 1, skv + AKV, tid);

    uint32_t qf[4][4];
    float o[8][4] = {};
    float l0 = 0.0f, l1 = 0.0f;
    const float sc = 0.125f;   // ||q||=||k||=8 exactly => fixed softmax max 8

#pragma unroll 1
    for (int t = 0; t < 8; t++) {
        if (t < 7) asm volatile("cp.async.wait_group 1;" ::: "memory");
        else       asm volatile("cp.async.wait_group 0;" ::: "memory");
        __syncthreads();
        if (t + 2 < 8)
            attn_ldkv(kb, vb, t + 2, skv + ((t + 2) % 3) * AKV, tid);

        if (t == 0) {
#pragma unroll
            for (int kk = 0; kk < 4; kk++)
                ldm_x4(qf[kk], sq + (wid * 16 + (lane & 15)) * 144 + (lane >> 4) * 16 + kk * 32);
        }

        const uint32_t skb = skv + (t % 3) * AKV;
        const uint32_t svb = skb + 9216;

        float sacc[8][4] = {};
#pragma unroll
        for (int kk = 0; kk < 4; kk++) {
#pragma unroll
            for (int ntp = 0; ntp < 4; ntp++) {
                uint32_t kf[4];
                ldm_x4(kf, skb + (ntp * 16 + (lane & 7) + (lane >> 4) * 8) * 144
                           + ((lane >> 3) & 1) * 16 + kk * 32);
                mma_f16(sacc[2 * ntp],     qf[kk], kf);
                mma_f16(sacc[2 * ntp + 1], qf[kk], kf + 2);
            }
        }

        uint32_t pf[4][4];
        float rs0 = 0.0f, rs1 = 0.0f;
#pragma unroll
        for (int nt = 0; nt < 8; nt++) {
            float p0 = __expf(sacc[nt][0] * sc - 8.0f);
            float p1 = __expf(sacc[nt][1] * sc - 8.0f);
            float p2 = __expf(sacc[nt][2] * sc - 8.0f);
            float p3 = __expf(sacc[nt][3] * sc - 8.0f);
            rs0 += p0 + p1; rs1 += p2 + p3;
            __half2 h01 = __floats2half2_rn(p0, p1);
            __half2 h23 = __floats2half2_rn(p2, p3);
            pf[nt >> 1][(nt & 1) * 2]     = *(uint32_t*)&h01;
            pf[nt >> 1][(nt & 1) * 2 + 1] = *(uint32_t*)&h23;
        }
        l0 += rs0;
        l1 += rs1;

#pragma unroll
        for (int kg = 0; kg < 4; kg++) {
#pragma unroll
            for (int dtp = 0; dtp < 4; dtp++) {
                uint32_t vf[4];
                ldm_x4t(vf, svb + (kg * 16 + (lane & 15)) * 144
                            + (2 * dtp + (lane >> 4)) * 16);
                mma_f16(o[2 * dtp],     pf[kg], vf);
                mma_f16(o[2 * dtp + 1], pf[kg], vf + 2);
            }
        }
    }

    float l0t = l0 + __shfl_xor_sync(0xffffffffu, l0, 1);
    l0t += __shfl_xor_sync(0xffffffffu, l0t, 2);
    float l1t = l1 + __shfl_xor_sync(0xffffffffu, l1, 1);
    l1t += __shfl_xor_sync(0xffffffffu, l1t, 2);
    float inv0 = 1.0f / l0t, inv1 = 1.0f / l1t;

    const int w  = wh >> 4, h = wh & 15;
    const int wz = w >> 2, wy = (w >> 1) & 1, wx = w & 1;
    int lr[2] = {qt * 64 + wid * 16 + (lane >> 2), qt * 64 + wid * 16 + (lane >> 2) + 8};
    int ntok[2];
#pragma unroll
    for (int r = 0; r < 2; r++) {
        int li = lr[r];
        int lz = li >> 6, ly = (li >> 3) & 7, lx = li & 7;
        int z = wz * 8 + lz, y = wy * 8 + ly, x = wx * 8 + lx;
        ntok[r] = (z << 8) | (y << 4) | x;
    }
#pragma unroll
    for (int dt = 0; dt < 8; dt++) {
        int col = h * HD + dt * 8 + (lane & 3) * 2;
        *(__half2*)&g_as[(size_t)ntok[0] * KDIM + col] =
            __floats2half2_rn(o[dt][0] * inv0, o[dt][1] * inv0);
        *(__half2*)&g_as[(size_t)ntok[1] * KDIM + col] =
            __floats2half2_rn(o[dt][2] * inv1, o[dt][3] * inv1);
    }
}

// ---------------- launch ----------------
extern "C" void kernel_launch(void* const* d_in, const int* in_sizes, int n_in,
                              void* d_out, int out_size) {
    const float* x      = (const float*)d_in[0];
    const int*   coords = (const int*)  d_in[1];
    const float* wqkv   = (const float*)d_in[2];
    const float* bqkv   = (const float*)d_in[3];
    const float* qg     = (const float*)d_in[4];
    const float* kg     = (const float*)d_in[5];
    const float* wout   = (const float*)d_in[6];
    const float* bout   = (const float*)d_in[7];
    float* out = (float*)d_out;

    cudaFuncSetAttribute(attn_mma, cudaFuncAttributeMaxDynamicSharedMemorySize, ATTN_SMEM);
    cudaFuncSetAttribute(k_gemm_qkv, cudaFuncAttributeMaxDynamicSharedMemorySize, QKV_SMEM);
    cudaFuncSetAttribute(k_gemm_out, cudaFuncAttributeMaxDynamicSharedMemorySize, OUT_SMEM);

    k_conv_all<<<8192, 256>>>(x, wqkv, wout);
    k_gemm_qkv<<<dim3(C3 / BN, NTOK / 64), 256, QKV_SMEM>>>(bqkv, coords, qg, kg);
    attn_mma<<<dim3(NWIN * NH, LWIN / 64), 128, ATTN_SMEM>>>();
    k_gemm_out<<<dim3(CDIM / BN, NTOK / 128), 256, OUT_SMEM>>>(bout, out);
}

// round 15
// speedup vs baseline: 1.2514x; 1.2514x over previous
#include <cuda_runtime.h>
#include <cuda_bf16.h>
#include <cuda_fp16.h>
#include <cstdint>

#define NTOK 4096
#define CDIM 1024
#define C3   3072
#define NH   16
#define HD   64
#define LWIN 512
#define NWIN 8

#define BM 128
#define BN 128
#define BK 64
#define KDIM 1024
#define TSTEPS (KDIM / BK)       // 16
#define STAGEB 36864             // 256 rows x 144 B per stage
#define GEMM_SMEM (3 * STAGEB)   // 110592

#define AKV 18432                // attn K+V stage bytes (64*144*2)
#define ATTN_SMEM (18432 + 3 * AKV)   // Q + 3-stage KV ring = 73728

// ---------------- scratch ----------------
__device__ __half g_qh[NTOK * CDIM];     // [w][h][l][d] fp16
__device__ __half g_kh[NTOK * CDIM];
__device__ __half g_vh[NTOK * CDIM];
__device__ __half g_as[NTOK * KDIM];     // GEMM A buffer (x, then attention O)
__device__ __half g_bs[4096 * KDIM];     // GEMM B: rows 0..3071 wqkv^T, 3072..4095 wout^T

// ---------------- helpers ----------------
__device__ __forceinline__ uint32_t su32(const void* p) {
    uint32_t a;
    asm("{ .reg .u64 t; cvta.to.shared.u64 t, %1; cvt.u32.u64 %0, t; }" : "=r"(a) : "l"(p));
    return a;
}
__device__ __forceinline__ void cp16(uint32_t dst, const void* src) {
    asm volatile("cp.async.cg.shared.global [%0], [%1], 16;" :: "r"(dst), "l"(src));
}
__device__ __forceinline__ void ldm_x4(uint32_t* r, uint32_t addr) {
    asm volatile("ldmatrix.sync.aligned.m8n8.x4.shared.b16 {%0,%1,%2,%3}, [%4];"
                 : "=r"(r[0]), "=r"(r[1]), "=r"(r[2]), "=r"(r[3]) : "r"(addr));
}
__device__ __forceinline__ void ldm_x4t(uint32_t* r, uint32_t addr) {
    asm volatile("ldmatrix.sync.aligned.m8n8.x4.trans.shared.b16 {%0,%1,%2,%3}, [%4];"
                 : "=r"(r[0]), "=r"(r[1]), "=r"(r[2]), "=r"(r[3]) : "r"(addr));
}
__device__ __forceinline__ void ldm_x2(uint32_t* r, uint32_t addr) {
    asm volatile("ldmatrix.sync.aligned.m8n8.x2.shared.b16 {%0,%1}, [%2];"
                 : "=r"(r[0]), "=r"(r[1]) : "r"(addr));
}
__device__ __forceinline__ void mma_f16(float* c, const uint32_t* a, const uint32_t* b) {
    asm volatile("mma.sync.aligned.m16n8k16.row.col.f32.f16.f16.f32 "
                 "{%0,%1,%2,%3}, {%4,%5,%6,%7}, {%8,%9}, {%0,%1,%2,%3};"
                 : "+f"(c[0]), "+f"(c[1]), "+f"(c[2]), "+f"(c[3])
                 : "r"(a[0]), "r"(a[1]), "r"(a[2]), "r"(a[3]), "r"(b[0]), "r"(b[1]));
}

// ---------------- merged conversion kernel ----------------
__global__ __launch_bounds__(256) void k_conv_all(const float* __restrict__ x,
                                                  const float* __restrict__ wqkv,
                                                  const float* __restrict__ wout) {
    int bx = blockIdx.x;
    int tid = threadIdx.x;
    if (bx < 4096) {
        int idx = (bx * 256 + tid) << 2;
        float4 v = *(const float4*)&x[idx];
        __half2 h0 = __floats2half2_rn(v.x, v.y);
        __half2 h1 = __floats2half2_rn(v.z, v.w);
        uint2 hv;
        hv.x = *(uint32_t*)&h0;
        hv.y = *(uint32_t*)&h1;
        *(uint2*)(g_as + idx) = hv;
    } else {
        __shared__ float s[32][33];
        int b = bx - 4096;
        int tx = tid & 31, ty = tid >> 5;
        int bxx = b & 127, byy = b >> 7;
        const float* w;
        int N, n0;
        size_t off;
        if (bxx < 96) { w = wqkv; N = C3;   n0 = bxx * 32;        off = 0; }
        else          { w = wout; N = CDIM; n0 = (bxx - 96) * 32; off = (size_t)3072 * KDIM; }
        int k0 = byy * 32;
#pragma unroll
        for (int r = 0; r < 4; r++)
            s[ty + 8 * r][tx] = w[(size_t)(k0 + ty + 8 * r) * N + n0 + tx];
        __syncthreads();
#pragma unroll
        for (int r = 0; r < 4; r++) {
            int n = n0 + ty + 8 * r, k = k0 + tx;
            g_bs[off + (size_t)n * KDIM + k] = __float2half_rn(s[tx][ty + 8 * r]);
        }
    }
}

// ---------------- GEMM tile loader (BK=64: 256 rows x 144B) ----------------
__device__ __forceinline__ void issue_tile(const __half* __restrict__ A,
                                           const __half* __restrict__ B,
                                           int bm, int bn, int t,
                                           uint32_t sbase, int tid) {
    const int kt = t * BK;
#pragma unroll
    for (int p = 0; p < 4; p++) {              // A: 128 rows x 8 cp16
        int id = tid + p * 256;
        int row = id >> 3, cc = id & 7;
        cp16(sbase + row * 144 + cc * 16,
             A + (size_t)(bm + row) * KDIM + kt + cc * 8);
    }
#pragma unroll
    for (int p = 0; p < 4; p++) {              // B: 128 rows x 8 cp16
        int id = tid + p * 256;
        int row = id >> 3, cc = id & 7;
        cp16(sbase + 18432 + row * 144 + cc * 16,
             B + (size_t)(bn + row) * KDIM + kt + cc * 8);
    }
    asm volatile("cp.async.commit_group;" ::: "memory");
}

// mainloop (MT=4, BK=64, 16 steps, 64 MMAs per barrier window)
#define GEMM_MAINLOOP(Aptr, Bptr)                                                 \
    float c[4][4][4];                                                             \
    _Pragma("unroll")                                                             \
    for (int mt = 0; mt < 4; mt++)                                                \
        _Pragma("unroll")                                                         \
        for (int nt = 0; nt < 4; nt++)                                            \
            _Pragma("unroll")                                                     \
            for (int q = 0; q < 4; q++) c[mt][nt][q] = 0.0f;                      \
    const uint32_t aoff = (uint32_t)((wm * 64 + (lane & 15)) * 144 + (lane >> 4) * 16); \
    const uint32_t boff = (uint32_t)(18432 + (wn * 32 + (lane & 7)) * 144 + ((lane >> 3) & 1) * 16); \
    issue_tile(Aptr, Bptr, bm, bn, 0, base, tid);                                 \
    issue_tile(Aptr, Bptr, bm, bn, 1, base + STAGEB, tid);                        \
    _Pragma("unroll 1")                                                           \
    for (int t = 0; t < TSTEPS; t++) {                                            \
        if (t + 1 < TSTEPS) asm volatile("cp.async.wait_group 1;" ::: "memory");  \
        else                asm volatile("cp.async.wait_group 0;" ::: "memory");  \
        __syncthreads();                                                          \
        if (t + 2 < TSTEPS)                                                       \
            issue_tile(Aptr, Bptr, bm, bn, t + 2, base + ((t + 2) % 3) * STAGEB, tid); \
        const uint32_t stage = base + (t % 3) * STAGEB;                           \
        const uint32_t ab = stage + aoff;                                         \
        const uint32_t bb = stage + boff;                                         \
        _Pragma("unroll")                                                         \
        for (int ks = 0; ks < 4; ks++) {                                          \
            uint32_t af[4][4], bf[4][2];                                          \
            _Pragma("unroll")                                                     \
            for (int mt = 0; mt < 4; mt++)                                        \
                ldm_x4(af[mt], ab + mt * (16 * 144) + ks * 32);                   \
            _Pragma("unroll")                                                     \
            for (int nt = 0; nt < 4; nt++)                                        \
                ldm_x2(bf[nt], bb + nt * (8 * 144) + ks * 32);                    \
            _Pragma("unroll")                                                     \
            for (int mt = 0; mt < 4; mt++)                                        \
                _Pragma("unroll")                                                 \
                for (int nt = 0; nt < 4; nt++)                                    \
                    mma_f16(c[mt][nt], af[mt], bf[nt]);                           \
        }                                                                         \
    }

// ---------------- qkv GEMM with fused RMS-norm + RoPE + permute epilogue -------
__global__ __launch_bounds__(256, 2)
void k_gemm_qkv(const float* __restrict__ bias, const int* __restrict__ coords,
                const float* __restrict__ qg, const float* __restrict__ kg) {
    extern __shared__ __align__(16) char gsm[];
    const uint32_t base = su32(gsm);
    const int tid = threadIdx.x, wid = tid >> 5, lane = tid & 31;
    const int wm = wid & 1, wn = wid >> 1;
    const int bm = blockIdx.y * BM, bn = blockIdx.x * BN;

    GEMM_MAINLOOP(g_as, g_bs)

    // ---- fused epilogue ----
    __syncthreads();
    float* ssm = (float*)gsm;              // reuse: [wm(2)][wn(4)][64 rows]

    const int part  = bn >> 10;            // 0=q 1=k 2=v
    const int hglob = ((bn & 1023) >> 6) + (wn >> 1);
    const int c2    = (lane & 3) * 2;
    const int cihb  = (wn & 1) * 32 + c2;
    const int bcb   = bn + wn * 32 + c2;

    if (part < 2) {
        float ssv[4][2];
#pragma unroll
        for (int mt = 0; mt < 4; mt++) {
#pragma unroll
            for (int hf = 0; hf < 2; hf++) {
                float s = 0.0f;
#pragma unroll
                for (int nt = 0; nt < 4; nt++) {
                    float v0 = c[mt][nt][2 * hf]     + bias[bcb + nt * 8];
                    float v1 = c[mt][nt][2 * hf + 1] + bias[bcb + nt * 8 + 1];
                    s += v0 * v0 + v1 * v1;
                }
                s += __shfl_xor_sync(0xffffffffu, s, 1);
                s += __shfl_xor_sync(0xffffffffu, s, 2);
                ssv[mt][hf] = s;
            }
        }
        if ((lane & 3) == 0) {
#pragma unroll
            for (int mt = 0; mt < 4; mt++)
#pragma unroll
                for (int hf = 0; hf < 2; hf++)
                    ssm[(wm * 4 + wn) * 64 + mt * 16 + hf * 8 + (lane >> 2)] = ssv[mt][hf];
        }
        __syncthreads();

        const float* gam = (part == 0) ? qg : kg;
        __half* dst = (part == 0) ? g_qh : g_kh;
#pragma unroll
        for (int mt = 0; mt < 4; mt++) {
#pragma unroll
            for (int hf = 0; hf < 2; hf++) {
                int ridx = mt * 16 + hf * 8 + (lane >> 2);
                float tot = ssv[mt][hf] + ssm[(wm * 4 + (wn ^ 1)) * 64 + ridx];
                float inv = 8.0f / fmaxf(sqrtf(tot), 1e-12f);
                int n = bm + wm * 64 + ridx;
                int4 cd = *(const int4*)&coords[n * 4];
                int z = cd.y, y = cd.z, x = cd.w;
                int w = ((z >> 3) * 2 + (y >> 3)) * 2 + (x >> 3);
                int l = ((z & 7) * 8 + (y & 7)) * 8 + (x & 7);
                size_t ob = ((size_t)(w * NH + hglob) * LWIN + l) * HD;
#pragma unroll
                for (int nt = 0; nt < 4; nt++) {
                    int cih = cihb + nt * 8;
                    float re = (c[mt][nt][2 * hf]     + bias[bcb + nt * 8])     * inv * gam[hglob * HD + cih];
                    float im = (c[mt][nt][2 * hf + 1] + bias[bcb + nt * 8 + 1]) * inv * gam[hglob * HD + cih + 1];
                    int p = cih >> 1;
                    float cp = 1.0f, sp = 0.0f;
                    if (p < 30) {
                        int ax = p / 10, fi = p - ax * 10;
                        int cv = (ax == 0) ? z : (ax == 1) ? y : x;
                        __sincosf((float)cv * __expf(-(float)fi * 0.92103403719761836f), &sp, &cp);
                    }
                    *(__half2*)&dst[ob + cih] = __floats2half2_rn(re * cp - im * sp, re * sp + im * cp);
                }
            }
        }
    } else {
#pragma unroll
        for (int mt = 0; mt < 4; mt++) {
#pragma unroll
            for (int hf = 0; hf < 2; hf++) {
                int ridx = mt * 16 + hf * 8 + (lane >> 2);
                int n = bm + wm * 64 + ridx;
                int4 cd = *(const int4*)&coords[n * 4];
                int z = cd.y, y = cd.z, x = cd.w;
                int w = ((z >> 3) * 2 + (y >> 3)) * 2 + (x >> 3);
                int l = ((z & 7) * 8 + (y & 7)) * 8 + (x & 7);
                size_t ob = ((size_t)(w * NH + hglob) * LWIN + l) * HD;
#pragma unroll
                for (int nt = 0; nt < 4; nt++) {
                    int cih = cihb + nt * 8;
                    float v0 = c[mt][nt][2 * hf]     + bias[bcb + nt * 8];
                    float v1 = c[mt][nt][2 * hf + 1] + bias[bcb + nt * 8 + 1];
                    *(__half2*)&g_vh[ob + cih] = __floats2half2_rn(v0, v1);
                }
            }
        }
    }
}

// ---------------- out GEMM (fp32 output) ----------------
__global__ __launch_bounds__(256, 2)
void k_gemm_out(const float* __restrict__ bias, float* __restrict__ C) {
    extern __shared__ __align__(16) char gsm[];
    const uint32_t base = su32(gsm);
    const int tid = threadIdx.x, wid = tid >> 5, lane = tid & 31;
    const int wm = wid & 1, wn = wid >> 1;
    const int bm = blockIdx.y * BM, bn = blockIdx.x * BN;
    const __half* Bw = g_bs + (size_t)3072 * KDIM;

    GEMM_MAINLOOP(g_as, Bw)

    const int r0 = bm + wm * 64 + (lane >> 2);
    const int c0 = bn + wn * 32 + (lane & 3) * 2;
#pragma unroll
    for (int mt = 0; mt < 4; mt++) {
#pragma unroll
        for (int nt = 0; nt < 4; nt++) {
            int col = c0 + nt * 8;
            float bx = bias[col], by = bias[col + 1];
            int ra = r0 + mt * 16;
            *(float2*)&C[(size_t)ra * CDIM + col] =
                make_float2(c[mt][nt][0] + bx, c[mt][nt][1] + by);
            *(float2*)&C[(size_t)(ra + 8) * CDIM + col] =
                make_float2(c[mt][nt][2] + bx, c[mt][nt][3] + by);
        }
    }
}

// ---------------- fp16 flash attention (round-13 config) ----------------
__device__ __forceinline__ void attn_ldkv(const __half* kb, const __half* vb, int t,
                                          uint32_t stage, int tid) {
#pragma unroll
    for (int p = 0; p < 2; p++) {
        int id = tid + p * 256;
        int row = id >> 3, c = id & 7;
        cp16(stage + row * 144 + c * 16,        kb + (size_t)(t * 64 + row) * HD + c * 8);
        cp16(stage + 9216 + row * 144 + c * 16, vb + (size_t)(t * 64 + row) * HD + c * 8);
    }
    asm volatile("cp.async.commit_group;" ::: "memory");
}

__global__ __launch_bounds__(256, 2)
void attn_mma() {
    extern __shared__ __half asmem[];
    const int tid = threadIdx.x, wid = tid >> 5, lane = tid & 31;
    const int wh = blockIdx.x, qt = blockIdx.y;

    const uint32_t sq  = su32(asmem);
    const uint32_t skv = sq + 128 * 144;

    const __half* qb = g_qh + ((size_t)wh * LWIN + qt * 128) * HD;
    const __half* kb = g_kh + (size_t)wh * LWIN * HD;
    const __half* vb = g_vh + (size_t)wh * LWIN * HD;

#pragma unroll
    for (int p = 0; p < 4; p++) {
        int id = tid + p * 256;
        int row = id >> 3, c = id & 7;
        cp16(sq + row * 144 + c * 16, qb + (size_t)row * HD + c * 8);
    }
    attn_ldkv(kb, vb, 0, skv, tid);
    attn_ldkv(kb, vb, 1, skv + AKV, tid);

    uint32_t qf[4][4];
    float o[8][4] = {};
    float l0 = 0.0f, l1 = 0.0f;
    const float sc = 0.125f;   // ||q||=||k||=8 exactly => fixed softmax max 8

#pragma unroll 1
    for (int t = 0; t < 8; t++) {
        if (t < 7) asm volatile("cp.async.wait_group 1;" ::: "memory");
        else       asm volatile("cp.async.wait_group 0;" ::: "memory");
        __syncthreads();
        if (t + 2 < 8)
            attn_ldkv(kb, vb, t + 2, skv + ((t + 2) % 3) * AKV, tid);

        if (t == 0) {
#pragma unroll
            for (int kk = 0; kk < 4; kk++)
                ldm_x4(qf[kk], sq + (wid * 16 + (lane & 15)) * 144 + (lane >> 4) * 16 + kk * 32);
        }

        const uint32_t skb = skv + (t % 3) * AKV;
        const uint32_t svb = skb + 9216;

        float sacc[8][4] = {};
#pragma unroll
        for (int kk = 0; kk < 4; kk++) {
#pragma unroll
            for (int ntp = 0; ntp < 4; ntp++) {
                uint32_t kf[4];
                ldm_x4(kf, skb + (ntp * 16 + (lane & 7) + (lane >> 4) * 8) * 144
                           + ((lane >> 3) & 1) * 16 + kk * 32);
                mma_f16(sacc[2 * ntp],     qf[kk], kf);
                mma_f16(sacc[2 * ntp + 1], qf[kk], kf + 2);
            }
        }

        uint32_t pf[4][4];
        float rs0 = 0.0f, rs1 = 0.0f;
#pragma unroll
        for (int nt = 0; nt < 8; nt++) {
            float p0 = __expf(sacc[nt][0] * sc - 8.0f);
            float p1 = __expf(sacc[nt][1] * sc - 8.0f);
            float p2 = __expf(sacc[nt][2] * sc - 8.0f);
            float p3 = __expf(sacc[nt][3] * sc - 8.0f);
            rs0 += p0 + p1; rs1 += p2 + p3;
            __half2 h01 = __floats2half2_rn(p0, p1);
            __half2 h23 = __floats2half2_rn(p2, p3);
            pf[nt >> 1][(nt & 1) * 2]     = *(uint32_t*)&h01;
            pf[nt >> 1][(nt & 1) * 2 + 1] = *(uint32_t*)&h23;
        }
        l0 += rs0;
        l1 += rs1;

#pragma unroll
        for (int kg = 0; kg < 4; kg++) {
#pragma unroll
            for (int dtp = 0; dtp < 4; dtp++) {
                uint32_t vf[4];
                ldm_x4t(vf, svb + (kg * 16 + (lane & 15)) * 144
                            + (2 * dtp + (lane >> 4)) * 16);
                mma_f16(o[2 * dtp],     pf[kg], vf);
                mma_f16(o[2 * dtp + 1], pf[kg], vf + 2);
            }
        }
    }

    float l0t = l0 + __shfl_xor_sync(0xffffffffu, l0, 1);
    l0t += __shfl_xor_sync(0xffffffffu, l0t, 2);
    float l1t = l1 + __shfl_xor_sync(0xffffffffu, l1, 1);
    l1t += __shfl_xor_sync(0xffffffffu, l1t, 2);
    float inv0 = 1.0f / l0t, inv1 = 1.0f / l1t;

    const int w  = wh >> 4, h = wh & 15;
    const int wz = w >> 2, wy = (w >> 1) & 1, wx = w & 1;
    int lr[2] = {qt * 128 + wid * 16 + (lane >> 2), qt * 128 + wid * 16 + (lane >> 2) + 8};
    int ntok[2];
#pragma unroll
    for (int r = 0; r < 2; r++) {
        int li = lr[r];
        int lz = li >> 6, ly = (li >> 3) & 7, lx = li & 7;
        int z = wz * 8 + lz, y = wy * 8 + ly, x = wx * 8 + lx;
        ntok[r] = (z << 8) | (y << 4) | x;
    }
#pragma unroll
    for (int dt = 0; dt < 8; dt++) {
        int col = h * HD + dt * 8 + (lane & 3) * 2;
        *(__half2*)&g_as[(size_t)ntok[0] * KDIM + col] =
            __floats2half2_rn(o[dt][0] * inv0, o[dt][1] * inv0);
        *(__half2*)&g_as[(size_t)ntok[1] * KDIM + col] =
            __floats2half2_rn(o[dt][2] * inv1, o[dt][3] * inv1);
    }
}

// ---------------- launch ----------------
extern "C" void kernel_launch(void* const* d_in, const int* in_sizes, int n_in,
                              void* d_out, int out_size) {
    const float* x      = (const float*)d_in[0];
    const int*   coords = (const int*)  d_in[1];
    const float* wqkv   = (const float*)d_in[2];
    const float* bqkv   = (const float*)d_in[3];
    const float* qg     = (const float*)d_in[4];
    const float* kg     = (const float*)d_in[5];
    const float* wout   = (const float*)d_in[6];
    const float* bout   = (const float*)d_in[7];
    float* out = (float*)d_out;

    cudaFuncSetAttribute(attn_mma, cudaFuncAttributeMaxDynamicSharedMemorySize, ATTN_SMEM);
    cudaFuncSetAttribute(k_gemm_qkv, cudaFuncAttributeMaxDynamicSharedMemorySize, GEMM_SMEM);
    cudaFuncSetAttribute(k_gemm_out, cudaFuncAttributeMaxDynamicSharedMemorySize, GEMM_SMEM);

    k_conv_all<<<8192, 256>>>(x, wqkv, wout);
    k_gemm_qkv<<<dim3(C3 / BN, NTOK / BM), 256, GEMM_SMEM>>>(bqkv, coords, qg, kg);
    attn_mma<<<dim3(NWIN * NH, LWIN / 128), 256, ATTN_SMEM>>>();
    k_gemm_out<<<dim3(CDIM / BN, NTOK / BM), 256, GEMM_SMEM>>>(bout, out);
}

// round 17
// speedup vs baseline: 1.2866x; 1.0281x over previous
#include <cuda_runtime.h>
#include <cuda_bf16.h>
#include <cuda_fp16.h>
#include <cstdint>

#define NTOK 4096
#define CDIM 1024
#define C3   3072
#define NH   16
#define HD   64
#define LWIN 512
#define NWIN 8

#define BM 128
#define BN 128
#define BK 64
#define KDIM 1024
#define TSTEPS (KDIM / BK)       // 16
#define STAGEB 36864             // 256 rows x 144 B per stage
#define GEMM_SMEM (3 * STAGEB)   // 110592

#define AKV 18432                // attn K+V stage bytes (64*144*2)
#define ATTN_SMEM (18432 + 3 * AKV)   // Q + 3-stage KV ring = 73728

// ---------------- scratch ----------------
__device__ __half g_qh[NTOK * CDIM];     // [w][h][l][d] fp16
__device__ __half g_kh[NTOK * CDIM];
__device__ __half g_vh[NTOK * CDIM];
__device__ __half g_as[NTOK * KDIM];     // GEMM A buffer (x, then attention O)
__device__ __half g_bs[4096 * KDIM];     // GEMM B: rows 0..3071 wqkv^T, 3072..4095 wout^T

// ---------------- helpers ----------------
__device__ __forceinline__ uint32_t su32(const void* p) {
    uint32_t a;
    asm("{ .reg .u64 t; cvta.to.shared.u64 t, %1; cvt.u32.u64 %0, t; }" : "=r"(a) : "l"(p));
    return a;
}
__device__ __forceinline__ void cp16(uint32_t dst, const void* src) {
    asm volatile("cp.async.cg.shared.global [%0], [%1], 16;" :: "r"(dst), "l"(src));
}
__device__ __forceinline__ void ldm_x4(uint32_t* r, uint32_t addr) {
    asm volatile("ldmatrix.sync.aligned.m8n8.x4.shared.b16 {%0,%1,%2,%3}, [%4];"
                 : "=r"(r[0]), "=r"(r[1]), "=r"(r[2]), "=r"(r[3]) : "r"(addr));
}
__device__ __forceinline__ void ldm_x4t(uint32_t* r, uint32_t addr) {
    asm volatile("ldmatrix.sync.aligned.m8n8.x4.trans.shared.b16 {%0,%1,%2,%3}, [%4];"
                 : "=r"(r[0]), "=r"(r[1]), "=r"(r[2]), "=r"(r[3]) : "r"(addr));
}
__device__ __forceinline__ void mma_f16(float* c, const uint32_t* a, const uint32_t* b) {
    asm volatile("mma.sync.aligned.m16n8k16.row.col.f32.f16.f16.f32 "
                 "{%0,%1,%2,%3}, {%4,%5,%6,%7}, {%8,%9}, {%0,%1,%2,%3};"
                 : "+f"(c[0]), "+f"(c[1]), "+f"(c[2]), "+f"(c[3])
                 : "r"(a[0]), "r"(a[1]), "r"(a[2]), "r"(a[3]), "r"(b[0]), "r"(b[1]));
}

// ---------------- merged conversion kernel ----------------
__global__ __launch_bounds__(256) void k_conv_all(const float* __restrict__ x,
                                                  const float* __restrict__ wqkv,
                                                  const float* __restrict__ wout) {
    int bx = blockIdx.x;
    int tid = threadIdx.x;
    if (bx < 4096) {
        int idx = (bx * 256 + tid) << 2;
        float4 v = *(const float4*)&x[idx];
        __half2 h0 = __floats2half2_rn(v.x, v.y);
        __half2 h1 = __floats2half2_rn(v.z, v.w);
        uint2 hv;
        hv.x = *(uint32_t*)&h0;
        hv.y = *(uint32_t*)&h1;
        *(uint2*)(g_as + idx) = hv;
    } else {
        __shared__ float s[32][33];
        int b = bx - 4096;
        int tx = tid & 31, ty = tid >> 5;
        int bxx = b & 127, byy = b >> 7;
        const float* w;
        int N, n0;
        size_t off;
        if (bxx < 96) { w = wqkv; N = C3;   n0 = bxx * 32;        off = 0; }
        else          { w = wout; N = CDIM; n0 = (bxx - 96) * 32; off = (size_t)3072 * KDIM; }
        int k0 = byy * 32;
#pragma unroll
        for (int r = 0; r < 4; r++)
            s[ty + 8 * r][tx] = w[(size_t)(k0 + ty + 8 * r) * N + n0 + tx];
        __syncthreads();
#pragma unroll
        for (int r = 0; r < 4; r++) {
            int n = n0 + ty + 8 * r, k = k0 + tx;
            g_bs[off + (size_t)n * KDIM + k] = __float2half_rn(s[tx][ty + 8 * r]);
        }
    }
}

// ---------------- GEMM tile loader (BK=64: 256 rows x 144B) ----------------
__device__ __forceinline__ void issue_tile(const __half* __restrict__ A,
                                           const __half* __restrict__ B,
                                           int bm, int bn, int t,
                                           uint32_t sbase, int tid) {
    const int kt = t * BK;
#pragma unroll
    for (int p = 0; p < 4; p++) {              // A: 128 rows x 8 cp16
        int id = tid + p * 256;
        int row = id >> 3, cc = id & 7;
        cp16(sbase + row * 144 + cc * 16,
             A + (size_t)(bm + row) * KDIM + kt + cc * 8);
    }
#pragma unroll
    for (int p = 0; p < 4; p++) {              // B: 128 rows x 8 cp16
        int id = tid + p * 256;
        int row = id >> 3, cc = id & 7;
        cp16(sbase + 18432 + row * 144 + cc * 16,
             B + (size_t)(bn + row) * KDIM + kt + cc * 8);
    }
    asm volatile("cp.async.commit_group;" ::: "memory");
}

// mainloop (MT=4, BK=64; B fragments via ldm_x4 — two nt per ldsm, all lanes used)
#define GEMM_MAINLOOP(Aptr, Bptr)                                                 \
    float c[4][4][4];                                                             \
    _Pragma("unroll")                                                             \
    for (int mt = 0; mt < 4; mt++)                                                \
        _Pragma("unroll")                                                         \
        for (int nt = 0; nt < 4; nt++)                                            \
            _Pragma("unroll")                                                     \
            for (int q = 0; q < 4; q++) c[mt][nt][q] = 0.0f;                      \
    const uint32_t aoff = (uint32_t)((wm * 64 + (lane & 15)) * 144 + (lane >> 4) * 16); \
    const uint32_t boff = (uint32_t)(18432 + (wn * 32 + (lane & 7) + ((lane >> 4) * 8)) * 144 + ((lane >> 3) & 1) * 16); \
    issue_tile(Aptr, Bptr, bm, bn, 0, base, tid);                                 \
    issue_tile(Aptr, Bptr, bm, bn, 1, base + STAGEB, tid);                        \
    _Pragma("unroll 1")                                                           \
    for (int t = 0; t < TSTEPS; t++) {                                            \
        if (t + 1 < TSTEPS) asm volatile("cp.async.wait_group 1;" ::: "memory");  \
        else                asm volatile("cp.async.wait_group 0;" ::: "memory");  \
        __syncthreads();                                                          \
        if (t + 2 < TSTEPS)                                                       \
            issue_tile(Aptr, Bptr, bm, bn, t + 2, base + ((t + 2) % 3) * STAGEB, tid); \
        const uint32_t stage = base + (t % 3) * STAGEB;                           \
        const uint32_t ab = stage + aoff;                                         \
        const uint32_t bb = stage + boff;                                         \
        _Pragma("unroll")                                                         \
        for (int ks = 0; ks < 4; ks++) {                                          \
            uint32_t af[4][4], bf[2][4];                                          \
            _Pragma("unroll")                                                     \
            for (int mt = 0; mt < 4; mt++)                                        \
                ldm_x4(af[mt], ab + mt * (16 * 144) + ks * 32);                   \
            _Pragma("unroll")                                                     \
            for (int np = 0; np < 2; np++)                                        \
                ldm_x4(bf[np], bb + np * (16 * 144) + ks * 32);                   \
            _Pragma("unroll")                                                     \
            for (int mt = 0; mt < 4; mt++)                                        \
                _Pragma("unroll")                                                 \
                for (int nt = 0; nt < 4; nt++)                                    \
                    mma_f16(c[mt][nt], af[mt], bf[nt >> 1] + (nt & 1) * 2);       \
        }                                                                         \
    }

// ---------------- qkv GEMM with fused RMS-norm + RoPE + permute epilogue -------
__global__ __launch_bounds__(256, 2)
void k_gemm_qkv(const float* __restrict__ bias, const int* __restrict__ coords,
                const float* __restrict__ qg, const float* __restrict__ kg) {
    extern __shared__ __align__(16) char gsm[];
    const uint32_t base = su32(gsm);
    const int tid = threadIdx.x, wid = tid >> 5, lane = tid & 31;
    const int wm = wid & 1, wn = wid >> 1;
    const int bm = blockIdx.y * BM, bn = blockIdx.x * BN;

    GEMM_MAINLOOP(g_as, g_bs)

    // ---- fused epilogue ----
    __syncthreads();
    float* ssm = (float*)gsm;              // reuse: [wm(2)][wn(4)][64 rows]

    const int part  = bn >> 10;            // 0=q 1=k 2=v
    const int hglob = ((bn & 1023) >> 6) + (wn >> 1);
    const int c2    = (lane & 3) * 2;
    const int cihb  = (wn & 1) * 32 + c2;
    const int bcb   = bn + wn * 32 + c2;

    if (part < 2) {
        float ssv[4][2];
#pragma unroll
        for (int mt = 0; mt < 4; mt++) {
#pragma unroll
            for (int hf = 0; hf < 2; hf++) {
                float s = 0.0f;
#pragma unroll
                for (int nt = 0; nt < 4; nt++) {
                    float v0 = c[mt][nt][2 * hf]     + bias[bcb + nt * 8];
                    float v1 = c[mt][nt][2 * hf + 1] + bias[bcb + nt * 8 + 1];
                    s += v0 * v0 + v1 * v1;
                }
                s += __shfl_xor_sync(0xffffffffu, s, 1);
                s += __shfl_xor_sync(0xffffffffu, s, 2);
                ssv[mt][hf] = s;
            }
        }
        if ((lane & 3) == 0) {
#pragma unroll
            for (int mt = 0; mt < 4; mt++)
#pragma unroll
                for (int hf = 0; hf < 2; hf++)
                    ssm[(wm * 4 + wn) * 64 + mt * 16 + hf * 8 + (lane >> 2)] = ssv[mt][hf];
        }
        __syncthreads();

        const float* gam = (part == 0) ? qg : kg;
        __half* dst = (part == 0) ? g_qh : g_kh;
#pragma unroll
        for (int mt = 0; mt < 4; mt++) {
#pragma unroll
            for (int hf = 0; hf < 2; hf++) {
                int ridx = mt * 16 + hf * 8 + (lane >> 2);
                float tot = ssv[mt][hf] + ssm[(wm * 4 + (wn ^ 1)) * 64 + ridx];
                float inv = 8.0f / fmaxf(sqrtf(tot), 1e-12f);
                int n = bm + wm * 64 + ridx;
                int4 cd = *(const int4*)&coords[n * 4];
                int z = cd.y, y = cd.z, x = cd.w;
                int w = ((z >> 3) * 2 + (y >> 3)) * 2 + (x >> 3);
                int l = ((z & 7) * 8 + (y & 7)) * 8 + (x & 7);
                size_t ob = ((size_t)(w * NH + hglob) * LWIN + l) * HD;
#pragma unroll
                for (int nt = 0; nt < 4; nt++) {
                    int cih = cihb + nt * 8;
                    float re = (c[mt][nt][2 * hf]     + bias[bcb + nt * 8])     * inv * gam[hglob * HD + cih];
                    float im = (c[mt][nt][2 * hf + 1] + bias[bcb + nt * 8 + 1]) * inv * gam[hglob * HD + cih + 1];
                    int p = cih >> 1;
                    float cp = 1.0f, sp = 0.0f;
                    if (p < 30) {
                        int ax = p / 10, fi = p - ax * 10;
                        int cv = (ax == 0) ? z : (ax == 1) ? y : x;
                        __sincosf((float)cv * __expf(-(float)fi * 0.92103403719761836f), &sp, &cp);
                    }
                    *(__half2*)&dst[ob + cih] = __floats2half2_rn(re * cp - im * sp, re * sp + im * cp);
                }
            }
        }
    } else {
#pragma unroll
        for (int mt = 0; mt < 4; mt++) {
#pragma unroll
            for (int hf = 0; hf < 2; hf++) {
                int ridx = mt * 16 + hf * 8 + (lane >> 2);
                int n = bm + wm * 64 + ridx;
                int4 cd = *(const int4*)&coords[n * 4];
                int z = cd.y, y = cd.z, x = cd.w;
                int w = ((z >> 3) * 2 + (y >> 3)) * 2 + (x >> 3);
                int l = ((z & 7) * 8 + (y & 7)) * 8 + (x & 7);
                size_t ob = ((size_t)(w * NH + hglob) * LWIN + l) * HD;
#pragma unroll
                for (int nt = 0; nt < 4; nt++) {
                    int cih = cihb + nt * 8;
                    float v0 = c[mt][nt][2 * hf]     + bias[bcb + nt * 8];
                    float v1 = c[mt][nt][2 * hf + 1] + bias[bcb + nt * 8 + 1];
                    *(__half2*)&g_vh[ob + cih] = __floats2half2_rn(v0, v1);
                }
            }
        }
    }
}

// ---------------- out GEMM (fp32 output) ----------------
__global__ __launch_bounds__(256, 2)
void k_gemm_out(const float* __restrict__ bias, float* __restrict__ C) {
    extern __shared__ __align__(16) char gsm[];
    const uint32_t base = su32(gsm);
    const int tid = threadIdx.x, wid = tid >> 5, lane = tid & 31;
    const int wm = wid & 1, wn = wid >> 1;
    const int bm = blockIdx.y * BM, bn = blockIdx.x * BN;
    const __half* Bw = g_bs + (size_t)3072 * KDIM;

    GEMM_MAINLOOP(g_as, Bw)

    const int r0 = bm + wm * 64 + (lane >> 2);
    const int c0 = bn + wn * 32 + (lane & 3) * 2;
#pragma unroll
    for (int mt = 0; mt < 4; mt++) {
#pragma unroll
        for (int nt = 0; nt < 4; nt++) {
            int col = c0 + nt * 8;
            float bx = bias[col], by = bias[col + 1];
            int ra = r0 + mt * 16;
            *(float2*)&C[(size_t)ra * CDIM + col] =
                make_float2(c[mt][nt][0] + bx, c[mt][nt][1] + by);
            *(float2*)&C[(size_t)(ra + 8) * CDIM + col] =
                make_float2(c[mt][nt][2] + bx, c[mt][nt][3] + by);
        }
    }
}

// ---------------- fp16 flash attention (round-13 config) ----------------
__device__ __forceinline__ void attn_ldkv(const __half* kb, const __half* vb, int t,
                                          uint32_t stage, int tid) {
#pragma unroll
    for (int p = 0; p < 2; p++) {
        int id = tid + p * 256;
        int row = id >> 3, c = id & 7;
        cp16(stage + row * 144 + c * 16,        kb + (size_t)(t * 64 + row) * HD + c * 8);
        cp16(stage + 9216 + row * 144 + c * 16, vb + (size_t)(t * 64 + row) * HD + c * 8);
    }
    asm volatile("cp.async.commit_group;" ::: "memory");
}

__global__ __launch_bounds__(256, 2)
void attn_mma() {
    extern __shared__ __half asmem[];
    const int tid = threadIdx.x, wid = tid >> 5, lane = tid & 31;
    const int wh = blockIdx.x, qt = blockIdx.y;

    const uint32_t sq  = su32(asmem);
    const uint32_t skv = sq + 128 * 144;

    const __half* qb = g_qh + ((size_t)wh * LWIN + qt * 128) * HD;
    const __half* kb = g_kh + (size_t)wh * LWIN * HD;
    const __half* vb = g_vh + (size_t)wh * LWIN * HD;

#pragma unroll
    for (int p = 0; p < 4; p++) {
        int id = tid + p * 256;
        int row = id >> 3, c = id & 7;
        cp16(sq + row * 144 + c * 16, qb + (size_t)row * HD + c * 8);
    }
    attn_ldkv(kb, vb, 0, skv, tid);
    attn_ldkv(kb, vb, 1, skv + AKV, tid);

    uint32_t qf[4][4];
    float o[8][4] = {};
    float l0 = 0.0f, l1 = 0.0f;
    const float sc = 0.125f;   // ||q||=||k||=8 exactly => fixed softmax max 8

#pragma unroll 1
    for (int t = 0; t < 8; t++) {
        if (t < 7) asm volatile("cp.async.wait_group 1;" ::: "memory");
        else       asm volatile("cp.async.wait_group 0;" ::: "memory");
        __syncthreads();
        if (t + 2 < 8)
            attn_ldkv(kb, vb, t + 2, skv + ((t + 2) % 3) * AKV, tid);

        if (t == 0) {
#pragma unroll
            for (int kk = 0; kk < 4; kk++)
                ldm_x4(qf[kk], sq + (wid * 16 + (lane & 15)) * 144 + (lane >> 4) * 16 + kk * 32);
        }

        const uint32_t skb = skv + (t % 3) * AKV;
        const uint32_t svb = skb + 9216;

        float sacc[8][4] = {};
#pragma unroll
        for (int kk = 0; kk < 4; kk++) {
#pragma unroll
            for (int ntp = 0; ntp < 4; ntp++) {
                uint32_t kf[4];
                ldm_x4(kf, skb + (ntp * 16 + (lane & 7) + (lane >> 4) * 8) * 144
                           + ((lane >> 3) & 1) * 16 + kk * 32);
                mma_f16(sacc[2 * ntp],     qf[kk], kf);
                mma_f16(sacc[2 * ntp + 1], qf[kk], kf + 2);
            }
        }

        uint32_t pf[4][4];
        float rs0 = 0.0f, rs1 = 0.0f;
#pragma unroll
        for (int nt = 0; nt < 8; nt++) {
            float p0 = __expf(sacc[nt][0] * sc - 8.0f);
            float p1 = __expf(sacc[nt][1] * sc - 8.0f);
            float p2 = __expf(sacc[nt][2] * sc - 8.0f);
            float p3 = __expf(sacc[nt][3] * sc - 8.0f);
            rs0 += p0 + p1; rs1 += p2 + p3;
            __half2 h01 = __floats2half2_rn(p0, p1);
            __half2 h23 = __floats2half2_rn(p2, p3);
            pf[nt >> 1][(nt & 1) * 2]     = *(uint32_t*)&h01;
            pf[nt >> 1][(nt & 1) * 2 + 1] = *(uint32_t*)&h23;
        }
        l0 += rs0;
        l1 += rs1;

#pragma unroll
        for (int kg = 0; kg < 4; kg++) {
#pragma unroll
            for (int dtp = 0; dtp < 4; dtp++) {
                uint32_t vf[4];
                ldm_x4t(vf, svb + (kg * 16 + (lane & 15)) * 144
                            + (2 * dtp + (lane >> 4)) * 16);
                mma_f16(o[2 * dtp],     pf[kg], vf);
                mma_f16(o[2 * dtp + 1], pf[kg], vf + 2);
            }
        }
    }

    float l0t = l0 + __shfl_xor_sync(0xffffffffu, l0, 1);
    l0t += __shfl_xor_sync(0xffffffffu, l0t, 2);
    float l1t = l1 + __shfl_xor_sync(0xffffffffu, l1, 1);
    l1t += __shfl_xor_sync(0xffffffffu, l1t, 2);
    float inv0 = 1.0f / l0t, inv1 = 1.0f / l1t;

    const int w  = wh >> 4, h = wh & 15;
    const int wz = w >> 2, wy = (w >> 1) & 1, wx = w & 1;
    int lr[2] = {qt * 128 + wid * 16 + (lane >> 2), qt * 128 + wid * 16 + (lane >> 2) + 8};
    int ntok[2];
#pragma unroll
    for (int r = 0; r < 2; r++) {
        int li = lr[r];
        int lz = li >> 6, ly = (li >> 3) & 7, lx = li & 7;
        int z = wz * 8 + lz, y = wy * 8 + ly, x = wx * 8 + lx;
        ntok[r] = (z << 8) | (y << 4) | x;
    }
#pragma unroll
    for (int dt = 0; dt < 8; dt++) {
        int col = h * HD + dt * 8 + (lane & 3) * 2;
        *(__half2*)&g_as[(size_t)ntok[0] * KDIM + col] =
            __floats2half2_rn(o[dt][0] * inv0, o[dt][1] * inv0);
        *(__half2*)&g_as[(size_t)ntok[1] * KDIM + col] =
            __floats2half2_rn(o[dt][2] * inv1, o[dt][3] * inv1);
    }
}

// ---------------- launch ----------------
extern "C" void kernel_launch(void* const* d_in, const int* in_sizes, int n_in,
                              void* d_out, int out_size) {
    const float* x      = (const float*)d_in[0];
    const int*   coords = (const int*)  d_in[1];
    const float* wqkv   = (const float*)d_in[2];
    const float* bqkv   = (const float*)d_in[3];
    const float* qg     = (const float*)d_in[4];
    const float* kg     = (const float*)d_in[5];
    const float* wout   = (const float*)d_in[6];
    const float* bout   = (const float*)d_in[7];
    float* out = (float*)d_out;

    cudaFuncSetAttribute(attn_mma, cudaFuncAttributeMaxDynamicSharedMemorySize, ATTN_SMEM);
    cudaFuncSetAttribute(k_gemm_qkv, cudaFuncAttributeMaxDynamicSharedMemorySize, GEMM_SMEM);
    cudaFuncSetAttribute(k_gemm_out, cudaFuncAttributeMaxDynamicSharedMemorySize, GEMM_SMEM);

    k_conv_all<<<8192, 256>>>(x, wqkv, wout);
    k_gemm_qkv<<<dim3(C3 / BN, NTOK / BM), 256, GEMM_SMEM>>>(bqkv, coords, qg, kg);
    attn_mma<<<dim3(NWIN * NH, LWIN / 128), 256, ATTN_SMEM>>>();
    k_gemm_out<<<dim3(CDIM / BN, NTOK / BM), 256, GEMM_SMEM>>>(bout, out);
}